// round 11
// baseline (speedup 1.0000x reference)
#include <cuda_runtime.h>

#define AA 64
#define NN 128
#define HH 8
#define G2 2
#define THREADS 256
#define OUTW (AA - 1)          // 63
#define OUT_PER (AA * OUTW)    // 4032 floats per (t,b) tile
#define OUT4_PER (OUT_PER / 4) // 1008 float4
#define SR4 33                 // stage row stride in float4
#define AROW 68                // raw att row stride in floats
#define SQR 12                 // s_q row stride in floats

#define ST_F4   (AA * SR4)                 // float4 per staged tile (2112)
#define STAGE_ITERS (G2 * AA * NN / 4 / THREADS)   // 16
#define SMEM_BYTES (G2 * ST_F4 * 16 + NN * 16 * 4 + G2 * AA * SQR * 4 + G2 * AA * HH * 4)

typedef unsigned long long u64;

// ---- packed f32x2 helpers (Blackwell FFMA2) ----
__device__ __forceinline__ u64 pk2(float lo, float hi) {
    u64 r;
    asm("mov.b64 %0, {%1, %2};" : "=l"(r) : "f"(lo), "f"(hi));
    return r;
}
__device__ __forceinline__ void upk2(u64 v, float &lo, float &hi) {
    asm("mov.b64 {%0, %1}, %2;" : "=f"(lo), "=f"(hi) : "l"(v));
}
__device__ __forceinline__ void ffma2(u64 &d, u64 a, u64 b) {
    asm("fma.rn.f32x2 %0, %1, %2, %0;" : "+l"(d) : "l"(a), "l"(b));
}

__global__ void __launch_bounds__(THREADS, 2)
attn_kernel(const float* __restrict__ state,
            const float* __restrict__ Wq, const float* __restrict__ bq,
            const float* __restrict__ Wk, const float* __restrict__ bk,
            float* __restrict__ out)
{
    extern __shared__ __align__(16) unsigned char smem_raw[];
    float4* const s_x4 = (float4*)smem_raw;                       // [G2][ST_F4]
    float*  const s_w  = (float*)(smem_raw + G2 * ST_F4 * 16);    // NN*16
    float*  const s_q  = s_w + NN * 16;                           // [G2][AA*SQR]
    float*  const s_k  = s_q + G2 * AA * SQR;                     // [G2][AA*HH]

    const int tid = threadIdx.x;
    const int blk = blockIdx.x;

    // ---- weights: s_w[n*16 + 0..7] = Wq[n][:], s_w[n*16 + 8..15] = Wk[n][:]
    for (int i = tid; i < NN * HH; i += THREADS) {
        const int n = i >> 3, h = i & 7;
        s_w[n * 16 + h]     = Wq[i];
        s_w[n * 16 + 8 + h] = Wk[i];
    }

    // ---- Phase 0: coalesced stage of BOTH tiles (warp == one row, 512B)
    const float4* gsrc = (const float4*)(state + (size_t)blk * (G2 * AA * NN));
    #pragma unroll
    for (int k = 0; k < STAGE_ITERS; k++) {         // 16 iters, idx 0..4095
        const int idx = k * THREADS + tid;
        const int g = idx >> 11;                    // 0..1
        const int w = (idx >> 5) & 63;              // row within tile
        const int c = idx & 31;
        s_x4[g * ST_F4 + w * SR4 + c] = gsrc[idx];
    }
    __syncthreads();

    // ---- Phase 1: projection. thread = (mat, row); 128 active threads.
    if (tid < 2 * AA) {
        const int mat = tid >> 6;   // 0 = Q, 1 = K (uniform per warp)
        const int row = tid & 63;

        const float* bb = mat ? bk : bq;
        u64 a0[4], a1[4];
        #pragma unroll
        for (int p = 0; p < 4; p++) {
            const u64 seed = pk2(__ldg(bb + 2 * p), __ldg(bb + 2 * p + 1));
            a0[p] = seed; a1[p] = seed;
        }

        const float4* xr0 = s_x4 + row * SR4;
        const float4* xr1 = s_x4 + ST_F4 + row * SR4;
        const ulonglong2* wp = (const ulonglong2*)(s_w + mat * 8); // n stride = 4

        #pragma unroll 4
        for (int i = 0; i < 32; i++) {
            const float4 x0 = xr0[i];
            const float4 x1 = xr1[i];
            u64 xx;
            {
                const ulonglong2 w0 = wp[(4 * i + 0) * 4];
                const ulonglong2 w1 = wp[(4 * i + 0) * 4 + 1];
                xx = pk2(x0.x, x0.x);
                ffma2(a0[0], xx, w0.x); ffma2(a0[1], xx, w0.y);
                ffma2(a0[2], xx, w1.x); ffma2(a0[3], xx, w1.y);
                xx = pk2(x1.x, x1.x);
                ffma2(a1[0], xx, w0.x); ffma2(a1[1], xx, w0.y);
                ffma2(a1[2], xx, w1.x); ffma2(a1[3], xx, w1.y);
            }
            {
                const ulonglong2 w0 = wp[(4 * i + 1) * 4];
                const ulonglong2 w1 = wp[(4 * i + 1) * 4 + 1];
                xx = pk2(x0.y, x0.y);
                ffma2(a0[0], xx, w0.x); ffma2(a0[1], xx, w0.y);
                ffma2(a0[2], xx, w1.x); ffma2(a0[3], xx, w1.y);
                xx = pk2(x1.y, x1.y);
                ffma2(a1[0], xx, w0.x); ffma2(a1[1], xx, w0.y);
                ffma2(a1[2], xx, w1.x); ffma2(a1[3], xx, w1.y);
            }
            {
                const ulonglong2 w0 = wp[(4 * i + 2) * 4];
                const ulonglong2 w1 = wp[(4 * i + 2) * 4 + 1];
                xx = pk2(x0.z, x0.z);
                ffma2(a0[0], xx, w0.x); ffma2(a0[1], xx, w0.y);
                ffma2(a0[2], xx, w1.x); ffma2(a0[3], xx, w1.y);
                xx = pk2(x1.z, x1.z);
                ffma2(a1[0], xx, w0.x); ffma2(a1[1], xx, w0.y);
                ffma2(a1[2], xx, w1.x); ffma2(a1[3], xx, w1.y);
            }
            {
                const ulonglong2 w0 = wp[(4 * i + 3) * 4];
                const ulonglong2 w1 = wp[(4 * i + 3) * 4 + 1];
                xx = pk2(x0.w, x0.w);
                ffma2(a0[0], xx, w0.x); ffma2(a0[1], xx, w0.y);
                ffma2(a0[2], xx, w1.x); ffma2(a0[3], xx, w1.y);
                xx = pk2(x1.w, x1.w);
                ffma2(a1[0], xx, w0.x); ffma2(a1[1], xx, w0.y);
                ffma2(a1[2], xx, w1.x); ffma2(a1[3], xx, w1.y);
            }
        }

        float v0, v1, v2, v3, v4, v5, v6, v7;
        if (mat == 0) {
            upk2(a0[0], v0, v1); upk2(a0[1], v2, v3);
            upk2(a0[2], v4, v5); upk2(a0[3], v6, v7);
            *(float4*)(s_q + row * SQR)     = make_float4(v0, v1, v2, v3);
            *(float4*)(s_q + row * SQR + 4) = make_float4(v4, v5, v6, v7);
            upk2(a1[0], v0, v1); upk2(a1[1], v2, v3);
            upk2(a1[2], v4, v5); upk2(a1[3], v6, v7);
            *(float4*)(s_q + AA * SQR + row * SQR)     = make_float4(v0, v1, v2, v3);
            *(float4*)(s_q + AA * SQR + row * SQR + 4) = make_float4(v4, v5, v6, v7);
        } else {
            upk2(a0[0], v0, v1); upk2(a0[1], v2, v3);
            upk2(a0[2], v4, v5); upk2(a0[3], v6, v7);
            *(float4*)(s_k + row * HH)     = make_float4(v0, v1, v2, v3);
            *(float4*)(s_k + row * HH + 4) = make_float4(v4, v5, v6, v7);
            upk2(a1[0], v0, v1); upk2(a1[1], v2, v3);
            upk2(a1[2], v4, v5); upk2(a1[3], v6, v7);
            *(float4*)(s_k + AA * HH + row * HH)     = make_float4(v0, v1, v2, v3);
            *(float4*)(s_k + AA * HH + row * HH + 4) = make_float4(v4, v5, v6, v7);
        }
    }
    __syncthreads();
    // stage buffers are dead; raw att[g] aliases stage half g.

    // ---- Phase 2a: raw att in (sub,row); k-loads warp-uniform --------------
    {
        const int p_sub = tid >> 6;
        const int p_row = tid & 63;
        const int jbase = p_sub * 16;
        #pragma unroll
        for (int g = 0; g < G2; g++) {
            const float* qg = s_q + g * AA * SQR;
            const float* kg = s_k + g * AA * HH;
            float* attg = (float*)s_x4 + g * (ST_F4 * 4);

            const float4 qa = *(const float4*)(qg + p_row * SQR);
            const float4 qb = *(const float4*)(qg + p_row * SQR + 4);
            const float qr[8] = {qa.x, qa.y, qa.z, qa.w, qb.x, qb.y, qb.z, qb.w};

            u64 at2[8];
            #pragma unroll
            for (int p = 0; p < 8; p++) at2[p] = 0ull;

            // reshape trick: kr[h][j] = k_flat[h*64 + j]; warp-uniform address
            #pragma unroll
            for (int h = 0; h < HH; h++) {
                const u64 qq = pk2(qr[h], qr[h]);
                const ulonglong2* kp = (const ulonglong2*)(kg + h * AA + jbase);
                const ulonglong2 k0 = kp[0], k1 = kp[1], k2 = kp[2], k3 = kp[3];
                ffma2(at2[0], qq, k0.x); ffma2(at2[1], qq, k0.y);
                ffma2(at2[2], qq, k1.x); ffma2(at2[3], qq, k1.y);
                ffma2(at2[4], qq, k2.x); ffma2(at2[5], qq, k2.y);
                ffma2(at2[6], qq, k3.x); ffma2(at2[7], qq, k3.y);
            }

            float a[16];
            #pragma unroll
            for (int p = 0; p < 8; p++) upk2(at2[p], a[2 * p], a[2 * p + 1]);

            float4* arow = (float4*)(attg + p_row * AROW + jbase);
            arow[0] = make_float4(a[0],  a[1],  a[2],  a[3]);
            arow[1] = make_float4(a[4],  a[5],  a[6],  a[7]);
            arow[2] = make_float4(a[8],  a[9],  a[10], a[11]);
            arow[3] = make_float4(a[12], a[13], a[14], a[15]);
        }
    }
    __syncthreads();

    // ---- Phase 2b: softmax in registers, then COMPACTED write --------------
    //      (diagonal removed at write time -> phase 3 is a pure linear copy)
    {
        const int row = tid >> 2;
        const int sub = tid & 3;
        const int jbase = sub * 16;

        float av[G2][16];
        #pragma unroll
        for (int g = 0; g < G2; g++) {
            const float* attg = (const float*)s_x4 + g * (ST_F4 * 4);
            const float4* arow = (const float4*)(attg + row * AROW + jbase);
            const float4 v0 = arow[0], v1 = arow[1], v2 = arow[2], v3 = arow[3];
            float a[16] = {v0.x, v0.y, v0.z, v0.w, v1.x, v1.y, v1.z, v1.w,
                           v2.x, v2.y, v2.z, v2.w, v3.x, v3.y, v3.z, v3.w};

            float m = a[0];
            #pragma unroll
            for (int c = 1; c < 16; c++) m = fmaxf(m, a[c]);
            m = fmaxf(m, __shfl_xor_sync(0xffffffffu, m, 1));
            m = fmaxf(m, __shfl_xor_sync(0xffffffffu, m, 2));

            float s = 0.f;
            #pragma unroll
            for (int c = 0; c < 16; c++) { a[c] = __expf(a[c] - m); s += a[c]; }
            s += __shfl_xor_sync(0xffffffffu, s, 1);
            s += __shfl_xor_sync(0xffffffffu, s, 2);
            const float rinv = __frcp_rn(s);

            #pragma unroll
            for (int c = 0; c < 16; c++) av[g][c] = a[c] * rinv;
        }
        __syncthreads();   // all raw-att reads done; safe to overlay compact

        #pragma unroll
        for (int g = 0; g < G2; g++) {
            float* cmp = (float*)s_x4 + g * (ST_F4 * 4);   // [AA][63] compact
            float* crow = cmp + row * OUTW;
            #pragma unroll
            for (int c = 0; c < 16; c++) {
                const int j = jbase + c;
                if (j != row) crow[j - (j > row)] = av[g][c];
            }
        }
    }
    __syncthreads();

    // ---- Phase 3: pure linear copy smem -> gmem ---------------------------
    #pragma unroll
    for (int g = 0; g < G2; g++) {
        const float4* cmp4 = (const float4*)((const float*)s_x4 + g * (ST_F4 * 4));
        float4* o4p = (float4*)(out + (size_t)(blk * G2 + g) * OUT_PER);
        #pragma unroll
        for (int it = 0; it < 4; it++) {
            const int o4 = it * THREADS + tid;
            if (o4 < OUT4_PER) o4p[o4] = cmp4[o4];
        }
    }
}

extern "C" void kernel_launch(void* const* d_in, const int* in_sizes, int n_in,
                              void* d_out, int out_size) {
    const float* state = (const float*)d_in[0];
    const float* Wq    = (const float*)d_in[1];
    const float* bq    = (const float*)d_in[2];
    const float* Wk    = (const float*)d_in[3];
    const float* bk    = (const float*)d_in[4];
    float* out = (float*)d_out;

    // Not a stream op: safe under graph capture; idempotent every call.
    cudaFuncSetAttribute(attn_kernel,
                         cudaFuncAttributeMaxDynamicSharedMemorySize,
                         SMEM_BYTES);

    const int tb = in_sizes[0] / (AA * NN);  // T*B = 16384 tiles
    attn_kernel<<<tb / G2, THREADS, SMEM_BYTES>>>(state, Wq, bq, Wk, bk, out);
}

// round 12
// speedup vs baseline: 1.2882x; 1.2882x over previous
#include <cuda_runtime.h>

#define AA 64
#define NN 128
#define HH 8
#define G2 2
#define THREADS 256
#define OUTW (AA - 1)          // 63
#define OUT_PER (AA * OUTW)    // 4032 floats per (t,b) tile
#define OUT4_PER (OUT_PER / 4) // 1008 float4
#define SR4 33                 // stage row stride in float4
#define AROW 68                // att row stride in floats
#define SQR 12                 // s_q row stride in floats

#define ST_F4   (AA * SR4)                 // float4 per staged tile (2112)
#define STAGE_ITERS (G2 * AA * NN / 4 / THREADS)   // 16
#define SMEM_BYTES (G2 * ST_F4 * 16 + NN * 16 * 4 + G2 * AA * SQR * 4 + G2 * AA * HH * 4)

typedef unsigned long long u64;

// ---- packed f32x2 helpers (Blackwell FFMA2) ----
__device__ __forceinline__ u64 pk2(float lo, float hi) {
    u64 r;
    asm("mov.b64 %0, {%1, %2};" : "=l"(r) : "f"(lo), "f"(hi));
    return r;
}
__device__ __forceinline__ void upk2(u64 v, float &lo, float &hi) {
    asm("mov.b64 {%0, %1}, %2;" : "=f"(lo), "=f"(hi) : "l"(v));
}
__device__ __forceinline__ void ffma2(u64 &d, u64 a, u64 b) {
    asm("fma.rn.f32x2 %0, %1, %2, %0;" : "+l"(d) : "l"(a), "l"(b));
}

__global__ void __launch_bounds__(THREADS, 2)
attn_kernel(const float* __restrict__ state,
            const float* __restrict__ Wq, const float* __restrict__ bq,
            const float* __restrict__ Wk, const float* __restrict__ bk,
            float* __restrict__ out)
{
    extern __shared__ __align__(16) unsigned char smem_raw[];
    float4* const s_x4 = (float4*)smem_raw;                       // [G2][ST_F4]
    float*  const s_w  = (float*)(smem_raw + G2 * ST_F4 * 16);    // NN*16
    float*  const s_q  = s_w + NN * 16;                           // [G2][AA*SQR]
    float*  const s_k  = s_q + G2 * AA * SQR;                     // [G2][AA*HH]

    const int tid = threadIdx.x;
    const int blk = blockIdx.x;

    // ---- weights: s_w[n*16 + 0..7] = Wq[n][:], s_w[n*16 + 8..15] = Wk[n][:]
    for (int i = tid; i < NN * HH; i += THREADS) {
        const int n = i >> 3, h = i & 7;
        s_w[n * 16 + h]     = Wq[i];
        s_w[n * 16 + 8 + h] = Wk[i];
    }

    // ---- Phase 0: coalesced stage of BOTH tiles (warp == one row, 512B)
    const float4* gsrc = (const float4*)(state + (size_t)blk * (G2 * AA * NN));
    #pragma unroll
    for (int k = 0; k < STAGE_ITERS; k++) {         // 16 iters, idx 0..4095
        const int idx = k * THREADS + tid;
        const int g = idx >> 11;                    // 0..1
        const int w = (idx >> 5) & 63;              // row within tile
        const int c = idx & 31;
        s_x4[g * ST_F4 + w * SR4 + c] = gsrc[idx];
    }
    __syncthreads();

    // ---- Phase 1: projection. thread = (mat, row); 128 active threads.
    //      mat warp-uniform -> w-LDS broadcast; w reused across both tiles.
    if (tid < 2 * AA) {
        const int mat = tid >> 6;   // 0 = Q, 1 = K (uniform per warp)
        const int row = tid & 63;

        const float* bb = mat ? bk : bq;
        u64 a0[4], a1[4];
        #pragma unroll
        for (int p = 0; p < 4; p++) {
            const u64 seed = pk2(__ldg(bb + 2 * p), __ldg(bb + 2 * p + 1));
            a0[p] = seed; a1[p] = seed;
        }

        const float4* xr0 = s_x4 + row * SR4;
        const float4* xr1 = s_x4 + ST_F4 + row * SR4;
        const ulonglong2* wp = (const ulonglong2*)(s_w + mat * 8); // n stride = 4

        #pragma unroll 4
        for (int i = 0; i < 32; i++) {
            const float4 x0 = xr0[i];
            const float4 x1 = xr1[i];
            u64 xx;
            {
                const ulonglong2 w0 = wp[(4 * i + 0) * 4];
                const ulonglong2 w1 = wp[(4 * i + 0) * 4 + 1];
                xx = pk2(x0.x, x0.x);
                ffma2(a0[0], xx, w0.x); ffma2(a0[1], xx, w0.y);
                ffma2(a0[2], xx, w1.x); ffma2(a0[3], xx, w1.y);
                xx = pk2(x1.x, x1.x);
                ffma2(a1[0], xx, w0.x); ffma2(a1[1], xx, w0.y);
                ffma2(a1[2], xx, w1.x); ffma2(a1[3], xx, w1.y);
            }
            {
                const ulonglong2 w0 = wp[(4 * i + 1) * 4];
                const ulonglong2 w1 = wp[(4 * i + 1) * 4 + 1];
                xx = pk2(x0.y, x0.y);
                ffma2(a0[0], xx, w0.x); ffma2(a0[1], xx, w0.y);
                ffma2(a0[2], xx, w1.x); ffma2(a0[3], xx, w1.y);
                xx = pk2(x1.y, x1.y);
                ffma2(a1[0], xx, w0.x); ffma2(a1[1], xx, w0.y);
                ffma2(a1[2], xx, w1.x); ffma2(a1[3], xx, w1.y);
            }
            {
                const ulonglong2 w0 = wp[(4 * i + 2) * 4];
                const ulonglong2 w1 = wp[(4 * i + 2) * 4 + 1];
                xx = pk2(x0.z, x0.z);
                ffma2(a0[0], xx, w0.x); ffma2(a0[1], xx, w0.y);
                ffma2(a0[2], xx, w1.x); ffma2(a0[3], xx, w1.y);
                xx = pk2(x1.z, x1.z);
                ffma2(a1[0], xx, w0.x); ffma2(a1[1], xx, w0.y);
                ffma2(a1[2], xx, w1.x); ffma2(a1[3], xx, w1.y);
            }
            {
                const ulonglong2 w0 = wp[(4 * i + 3) * 4];
                const ulonglong2 w1 = wp[(4 * i + 3) * 4 + 1];
                xx = pk2(x0.w, x0.w);
                ffma2(a0[0], xx, w0.x); ffma2(a0[1], xx, w0.y);
                ffma2(a0[2], xx, w1.x); ffma2(a0[3], xx, w1.y);
                xx = pk2(x1.w, x1.w);
                ffma2(a1[0], xx, w0.x); ffma2(a1[1], xx, w0.y);
                ffma2(a1[2], xx, w1.x); ffma2(a1[3], xx, w1.y);
            }
        }

        float v0, v1, v2, v3, v4, v5, v6, v7;
        if (mat == 0) {
            upk2(a0[0], v0, v1); upk2(a0[1], v2, v3);
            upk2(a0[2], v4, v5); upk2(a0[3], v6, v7);
            *(float4*)(s_q + row * SQR)     = make_float4(v0, v1, v2, v3);
            *(float4*)(s_q + row * SQR + 4) = make_float4(v4, v5, v6, v7);
            upk2(a1[0], v0, v1); upk2(a1[1], v2, v3);
            upk2(a1[2], v4, v5); upk2(a1[3], v6, v7);
            *(float4*)(s_q + AA * SQR + row * SQR)     = make_float4(v0, v1, v2, v3);
            *(float4*)(s_q + AA * SQR + row * SQR + 4) = make_float4(v4, v5, v6, v7);
        } else {
            upk2(a0[0], v0, v1); upk2(a0[1], v2, v3);
            upk2(a0[2], v4, v5); upk2(a0[3], v6, v7);
            *(float4*)(s_k + row * HH)     = make_float4(v0, v1, v2, v3);
            *(float4*)(s_k + row * HH + 4) = make_float4(v4, v5, v6, v7);
            upk2(a1[0], v0, v1); upk2(a1[1], v2, v3);
            upk2(a1[2], v4, v5); upk2(a1[3], v6, v7);
            *(float4*)(s_k + AA * HH + row * HH)     = make_float4(v0, v1, v2, v3);
            *(float4*)(s_k + AA * HH + row * HH + 4) = make_float4(v4, v5, v6, v7);
        }
    }
    __syncthreads();
    // stage buffers are dead; att[g] aliases stage half g.

    // ---- Phase 2 (fused): att + softmax in (row,sub); single normalized write
    //      k-load address = kg + h*64 + sub*16: only 4 distinct 16B addrs/warp
    //      -> 1 wavefront per LDS.128 even though not warp-uniform.
    {
        const int row = tid >> 2;
        const int sub = tid & 3;
        const int jbase = sub * 16;

        #pragma unroll
        for (int g = 0; g < G2; g++) {
            const float* qg = s_q + g * AA * SQR;
            const float* kg = s_k + g * AA * HH;
            float* attg = (float*)s_x4 + g * (ST_F4 * 4);

            const float4 qa = *(const float4*)(qg + row * SQR);
            const float4 qb = *(const float4*)(qg + row * SQR + 4);
            const float qr[8] = {qa.x, qa.y, qa.z, qa.w, qb.x, qb.y, qb.z, qb.w};

            u64 at2[8];
            #pragma unroll
            for (int p = 0; p < 8; p++) at2[p] = 0ull;

            // reshape trick: kr[h][j] = k_flat[h*64 + j]
            #pragma unroll
            for (int h = 0; h < HH; h++) {
                const u64 qq = pk2(qr[h], qr[h]);
                const ulonglong2* kp = (const ulonglong2*)(kg + h * AA + jbase);
                const ulonglong2 k0 = kp[0], k1 = kp[1], k2 = kp[2], k3 = kp[3];
                ffma2(at2[0], qq, k0.x); ffma2(at2[1], qq, k0.y);
                ffma2(at2[2], qq, k1.x); ffma2(at2[3], qq, k1.y);
                ffma2(at2[4], qq, k2.x); ffma2(at2[5], qq, k2.y);
                ffma2(at2[6], qq, k3.x); ffma2(at2[7], qq, k3.y);
            }

            float a[16];
            #pragma unroll
            for (int p = 0; p < 8; p++) upk2(at2[p], a[2 * p], a[2 * p + 1]);

            // softmax across the row: 16 local + shfl with the 3 sibling lanes
            float m = a[0];
            #pragma unroll
            for (int c = 1; c < 16; c++) m = fmaxf(m, a[c]);
            m = fmaxf(m, __shfl_xor_sync(0xffffffffu, m, 1));
            m = fmaxf(m, __shfl_xor_sync(0xffffffffu, m, 2));

            float s = 0.f;
            #pragma unroll
            for (int c = 0; c < 16; c++) { a[c] = __expf(a[c] - m); s += a[c]; }
            s += __shfl_xor_sync(0xffffffffu, s, 1);
            s += __shfl_xor_sync(0xffffffffu, s, 2);
            const float rinv = __frcp_rn(s);

            float4* arow = (float4*)(attg + row * AROW + jbase);
            arow[0] = make_float4(a[0]  * rinv, a[1]  * rinv, a[2]  * rinv, a[3]  * rinv);
            arow[1] = make_float4(a[4]  * rinv, a[5]  * rinv, a[6]  * rinv, a[7]  * rinv);
            arow[2] = make_float4(a[8]  * rinv, a[9]  * rinv, a[10] * rinv, a[11] * rinv);
            arow[3] = make_float4(a[12] * rinv, a[13] * rinv, a[14] * rinv, a[15] * rinv);
        }
    }
    __syncthreads();

    // ---- Phase 3: off-diagonal gather, coalesced float4 stores -------------
    #pragma unroll
    for (int g = 0; g < G2; g++) {
        const float* attg = (const float*)s_x4 + g * (ST_F4 * 4);
        float4* o4p = (float4*)(out + (size_t)(blk * G2 + g) * OUT_PER);
        #pragma unroll
        for (int it = 0; it < 4; it++) {
            const int o4 = it * THREADS + tid;
            if (o4 < OUT4_PER) {
                const unsigned o = (unsigned)o4 * 4u;
                float v[4];
                #pragma unroll
                for (int c = 0; c < 4; c++) {
                    const unsigned oc = o + c;
                    const unsigned rr = oc / OUTW;
                    const unsigned jj = oc - rr * OUTW;
                    const unsigned j  = jj + (jj >= rr ? 1u : 0u);
                    v[c] = attg[rr * AROW + j];
                }
                o4p[o4] = make_float4(v[0], v[1], v[2], v[3]);
            }
        }
    }
}

extern "C" void kernel_launch(void* const* d_in, const int* in_sizes, int n_in,
                              void* d_out, int out_size) {
    const float* state = (const float*)d_in[0];
    const float* Wq    = (const float*)d_in[1];
    const float* bq    = (const float*)d_in[2];
    const float* Wk    = (const float*)d_in[3];
    const float* bk    = (const float*)d_in[4];
    float* out = (float*)d_out;

    // Not a stream op: safe under graph capture; idempotent every call.
    cudaFuncSetAttribute(attn_kernel,
                         cudaFuncAttributeMaxDynamicSharedMemorySize,
                         SMEM_BYTES);

    const int tb = in_sizes[0] / (AA * NN);  // T*B = 16384 tiles
    attn_kernel<<<tb / G2, THREADS, SMEM_BYTES>>>(state, Wq, bq, Wk, bk, out);
}

// round 13
// speedup vs baseline: 1.5706x; 1.2193x over previous
#include <cuda_runtime.h>

#define AA 64
#define NN 128
#define HH 8
#define G2 2
#define THREADS 256
#define OUTW (AA - 1)          // 63
#define OUT_PER (AA * OUTW)    // 4032 floats per (t,b) tile
#define OUT4_PER (OUT_PER / 4) // 1008 float4
#define SR4 33                 // stage row stride in float4
#define AROW 68                // att row stride in floats
#define SQR 12                 // s_q row stride in floats

#define ST_F4   (AA * SR4)                 // float4 per staged tile (2112)
#define STAGE_ITERS (G2 * AA * NN / 4 / THREADS)   // 16
#define SMEM_BYTES (G2 * ST_F4 * 16 + NN * 16 * 4 + G2 * AA * SQR * 4 \
                    + G2 * AA * HH * 4 + 8 * 128 * 8)

typedef unsigned long long u64;

// ---- packed f32x2 helpers (Blackwell FFMA2/FADD2) ----
__device__ __forceinline__ u64 pk2(float lo, float hi) {
    u64 r;
    asm("mov.b64 %0, {%1, %2};" : "=l"(r) : "f"(lo), "f"(hi));
    return r;
}
__device__ __forceinline__ void upk2(u64 v, float &lo, float &hi) {
    asm("mov.b64 {%0, %1}, %2;" : "=f"(lo), "=f"(hi) : "l"(v));
}
__device__ __forceinline__ void ffma2(u64 &d, u64 a, u64 b) {
    asm("fma.rn.f32x2 %0, %1, %2, %0;" : "+l"(d) : "l"(a), "l"(b));
}
__device__ __forceinline__ u64 fadd2(u64 a, u64 b) {
    u64 r;
    asm("add.rn.f32x2 %0, %1, %2;" : "=l"(r) : "l"(a), "l"(b));
    return r;
}

__global__ void __launch_bounds__(THREADS, 2)
attn_kernel(const float* __restrict__ state,
            const float* __restrict__ Wq, const float* __restrict__ bq,
            const float* __restrict__ Wk, const float* __restrict__ bk,
            float* __restrict__ out)
{
    extern __shared__ __align__(16) unsigned char smem_raw[];
    float4* const s_x4 = (float4*)smem_raw;                       // [G2][ST_F4]
    float*  const s_w  = (float*)(smem_raw + G2 * ST_F4 * 16);    // NN*16
    float*  const s_q  = s_w + NN * 16;                           // [G2][AA*SQR]
    float*  const s_k  = s_q + G2 * AA * SQR;                     // [G2][AA*HH]
    u64*    const s_pp = (u64*)(s_k + G2 * AA * HH);              // [8][128] partials

    const int tid = threadIdx.x;
    const int blk = blockIdx.x;

    // ---- weights: s_w[n*16 + 0..7] = Wq[n][:], s_w[n*16 + 8..15] = Wk[n][:]
    for (int i = tid; i < NN * HH; i += THREADS) {
        const int n = i >> 3, h = i & 7;
        s_w[n * 16 + h]     = Wq[i];
        s_w[n * 16 + 8 + h] = Wk[i];
    }

    // ---- Phase 0: coalesced stage of BOTH tiles (warp == one row, 512B)
    const float4* gsrc = (const float4*)(state + (size_t)blk * (G2 * AA * NN));
    #pragma unroll
    for (int k = 0; k < STAGE_ITERS; k++) {         // 16 iters, idx 0..4095
        const int idx = k * THREADS + tid;
        const int g = idx >> 11;                    // 0..1
        const int w = (idx >> 5) & 63;              // row within tile
        const int c = idx & 31;
        s_x4[g * ST_F4 + w * SR4 + c] = gsrc[idx];
    }
    __syncthreads();

    // ---- Phase 1: projection. thread = (mat, n-half, row); ALL 256 active.
    //      mat,nh warp-uniform -> w-LDS broadcast; row dense -> x-LDS 4cyc.
    {
        const int mat = tid >> 7;        // 0 = Q, 1 = K (uniform per warp)
        const int nh  = (tid >> 6) & 1;  // n-half          (uniform per warp)
        const int row = tid & 63;
        const int widx = mat * 64 + row; // partial slot 0..127

        const float* bb = mat ? bk : bq;
        u64 a0[4], a1[4];
        #pragma unroll
        for (int p = 0; p < 4; p++) {
            u64 seed = 0ull;
            if (nh == 0) seed = pk2(__ldg(bb + 2 * p), __ldg(bb + 2 * p + 1));
            a0[p] = seed; a1[p] = seed;
        }

        const float4* xr0 = s_x4 + row * SR4 + nh * 16;
        const float4* xr1 = xr0 + ST_F4;
        // ulonglong2 index: n*4 + mat*2 ; this thread's n base = nh*64
        const ulonglong2* wp =
            ((const ulonglong2*)s_w) + (nh * 64) * 4 + mat * 2;

        #pragma unroll 4
        for (int i = 0; i < 16; i++) {
            const float4 x0 = xr0[i];
            const float4 x1 = xr1[i];
            u64 xx;
            {
                const ulonglong2 w0 = wp[(4 * i + 0) * 4];
                const ulonglong2 w1 = wp[(4 * i + 0) * 4 + 1];
                xx = pk2(x0.x, x0.x);
                ffma2(a0[0], xx, w0.x); ffma2(a0[1], xx, w0.y);
                ffma2(a0[2], xx, w1.x); ffma2(a0[3], xx, w1.y);
                xx = pk2(x1.x, x1.x);
                ffma2(a1[0], xx, w0.x); ffma2(a1[1], xx, w0.y);
                ffma2(a1[2], xx, w1.x); ffma2(a1[3], xx, w1.y);
            }
            {
                const ulonglong2 w0 = wp[(4 * i + 1) * 4];
                const ulonglong2 w1 = wp[(4 * i + 1) * 4 + 1];
                xx = pk2(x0.y, x0.y);
                ffma2(a0[0], xx, w0.x); ffma2(a0[1], xx, w0.y);
                ffma2(a0[2], xx, w1.x); ffma2(a0[3], xx, w1.y);
                xx = pk2(x1.y, x1.y);
                ffma2(a1[0], xx, w0.x); ffma2(a1[1], xx, w0.y);
                ffma2(a1[2], xx, w1.x); ffma2(a1[3], xx, w1.y);
            }
            {
                const ulonglong2 w0 = wp[(4 * i + 2) * 4];
                const ulonglong2 w1 = wp[(4 * i + 2) * 4 + 1];
                xx = pk2(x0.z, x0.z);
                ffma2(a0[0], xx, w0.x); ffma2(a0[1], xx, w0.y);
                ffma2(a0[2], xx, w1.x); ffma2(a0[3], xx, w1.y);
                xx = pk2(x1.z, x1.z);
                ffma2(a1[0], xx, w0.x); ffma2(a1[1], xx, w0.y);
                ffma2(a1[2], xx, w1.x); ffma2(a1[3], xx, w1.y);
            }
            {
                const ulonglong2 w0 = wp[(4 * i + 3) * 4];
                const ulonglong2 w1 = wp[(4 * i + 3) * 4 + 1];
                xx = pk2(x0.w, x0.w);
                ffma2(a0[0], xx, w0.x); ffma2(a0[1], xx, w0.y);
                ffma2(a0[2], xx, w1.x); ffma2(a0[3], xx, w1.y);
                xx = pk2(x1.w, x1.w);
                ffma2(a1[0], xx, w0.x); ffma2(a1[1], xx, w0.y);
                ffma2(a1[2], xx, w1.x); ffma2(a1[3], xx, w1.y);
            }
        }

        // nh=1 publishes partials (dense STS.64, conflict-free)
        if (nh == 1) {
            #pragma unroll
            for (int p = 0; p < 4; p++) {
                s_pp[p * 128 + widx]       = a0[p];
                s_pp[(4 + p) * 128 + widx] = a1[p];
            }
        }
        __syncthreads();

        // nh=0 folds in partner's half and writes q/k (R10 layout)
        if (nh == 0) {
            #pragma unroll
            for (int p = 0; p < 4; p++) {
                a0[p] = fadd2(a0[p], s_pp[p * 128 + widx]);
                a1[p] = fadd2(a1[p], s_pp[(4 + p) * 128 + widx]);
            }
            float v0, v1, v2, v3, v4, v5, v6, v7;
            if (mat == 0) {
                upk2(a0[0], v0, v1); upk2(a0[1], v2, v3);
                upk2(a0[2], v4, v5); upk2(a0[3], v6, v7);
                *(float4*)(s_q + row * SQR)     = make_float4(v0, v1, v2, v3);
                *(float4*)(s_q + row * SQR + 4) = make_float4(v4, v5, v6, v7);
                upk2(a1[0], v0, v1); upk2(a1[1], v2, v3);
                upk2(a1[2], v4, v5); upk2(a1[3], v6, v7);
                *(float4*)(s_q + AA * SQR + row * SQR)     = make_float4(v0, v1, v2, v3);
                *(float4*)(s_q + AA * SQR + row * SQR + 4) = make_float4(v4, v5, v6, v7);
            } else {
                upk2(a0[0], v0, v1); upk2(a0[1], v2, v3);
                upk2(a0[2], v4, v5); upk2(a0[3], v6, v7);
                *(float4*)(s_k + row * HH)     = make_float4(v0, v1, v2, v3);
                *(float4*)(s_k + row * HH + 4) = make_float4(v4, v5, v6, v7);
                upk2(a1[0], v0, v1); upk2(a1[1], v2, v3);
                upk2(a1[2], v4, v5); upk2(a1[3], v6, v7);
                *(float4*)(s_k + AA * HH + row * HH)     = make_float4(v0, v1, v2, v3);
                *(float4*)(s_k + AA * HH + row * HH + 4) = make_float4(v4, v5, v6, v7);
            }
        }
    }
    __syncthreads();
    // stage buffers are dead; att[g] aliases stage half g.

    // ---- Phase 2a: raw att in (sub,row); k-loads warp-uniform --------------
    {
        const int p_sub = tid >> 6;
        const int p_row = tid & 63;
        const int jbase = p_sub * 16;
        #pragma unroll
        for (int g = 0; g < G2; g++) {
            const float* qg = s_q + g * AA * SQR;
            const float* kg = s_k + g * AA * HH;
            float* attg = (float*)s_x4 + g * (ST_F4 * 4);

            const float4 qa = *(const float4*)(qg + p_row * SQR);
            const float4 qb = *(const float4*)(qg + p_row * SQR + 4);
            const float qr[8] = {qa.x, qa.y, qa.z, qa.w, qb.x, qb.y, qb.z, qb.w};

            u64 at2[8];
            #pragma unroll
            for (int p = 0; p < 8; p++) at2[p] = 0ull;

            // reshape trick: kr[h][j] = k_flat[h*64 + j]; warp-uniform address
            #pragma unroll
            for (int h = 0; h < HH; h++) {
                const u64 qq = pk2(qr[h], qr[h]);
                const ulonglong2* kp = (const ulonglong2*)(kg + h * AA + jbase);
                const ulonglong2 k0 = kp[0], k1 = kp[1], k2 = kp[2], k3 = kp[3];
                ffma2(at2[0], qq, k0.x); ffma2(at2[1], qq, k0.y);
                ffma2(at2[2], qq, k1.x); ffma2(at2[3], qq, k1.y);
                ffma2(at2[4], qq, k2.x); ffma2(at2[5], qq, k2.y);
                ffma2(at2[6], qq, k3.x); ffma2(at2[7], qq, k3.y);
            }

            float a[16];
            #pragma unroll
            for (int p = 0; p < 8; p++) upk2(at2[p], a[2 * p], a[2 * p + 1]);

            float4* arow = (float4*)(attg + p_row * AROW + jbase);
            arow[0] = make_float4(a[0],  a[1],  a[2],  a[3]);
            arow[1] = make_float4(a[4],  a[5],  a[6],  a[7]);
            arow[2] = make_float4(a[8],  a[9],  a[10], a[11]);
            arow[3] = make_float4(a[12], a[13], a[14], a[15]);
        }
    }
    __syncthreads();

    // ---- Phase 2b: softmax in (row,sub); shfl partners adjacent ------------
    {
        const int row = tid >> 2;
        const int sub = tid & 3;
        #pragma unroll
        for (int g = 0; g < G2; g++) {
            float* attg = (float*)s_x4 + g * (ST_F4 * 4);
            float4* arow = (float4*)(attg + row * AROW + sub * 16);
            const float4 v0 = arow[0], v1 = arow[1], v2 = arow[2], v3 = arow[3];
            float a[16] = {v0.x, v0.y, v0.z, v0.w, v1.x, v1.y, v1.z, v1.w,
                           v2.x, v2.y, v2.z, v2.w, v3.x, v3.y, v3.z, v3.w};

            float m = a[0];
            #pragma unroll
            for (int c = 1; c < 16; c++) m = fmaxf(m, a[c]);
            m = fmaxf(m, __shfl_xor_sync(0xffffffffu, m, 1));
            m = fmaxf(m, __shfl_xor_sync(0xffffffffu, m, 2));

            float s = 0.f;
            #pragma unroll
            for (int c = 0; c < 16; c++) { a[c] = __expf(a[c] - m); s += a[c]; }
            s += __shfl_xor_sync(0xffffffffu, s, 1);
            s += __shfl_xor_sync(0xffffffffu, s, 2);
            const float rinv = __frcp_rn(s);

            arow[0] = make_float4(a[0]  * rinv, a[1]  * rinv, a[2]  * rinv, a[3]  * rinv);
            arow[1] = make_float4(a[4]  * rinv, a[5]  * rinv, a[6]  * rinv, a[7]  * rinv);
            arow[2] = make_float4(a[8]  * rinv, a[9]  * rinv, a[10] * rinv, a[11] * rinv);
            arow[3] = make_float4(a[12] * rinv, a[13] * rinv, a[14] * rinv, a[15] * rinv);
        }
    }
    __syncthreads();

    // ---- Phase 3: off-diagonal gather, coalesced float4 stores -------------
    #pragma unroll
    for (int g = 0; g < G2; g++) {
        const float* attg = (const float*)s_x4 + g * (ST_F4 * 4);
        float4* o4p = (float4*)(out + (size_t)(blk * G2 + g) * OUT_PER);
        #pragma unroll
        for (int it = 0; it < 4; it++) {
            const int o4 = it * THREADS + tid;
            if (o4 < OUT4_PER) {
                const unsigned o = (unsigned)o4 * 4u;
                float v[4];
                #pragma unroll
                for (int c = 0; c < 4; c++) {
                    const unsigned oc = o + c;
                    const unsigned rr = oc / OUTW;
                    const unsigned jj = oc - rr * OUTW;
                    const unsigned j  = jj + (jj >= rr ? 1u : 0u);
                    v[c] = attg[rr * AROW + j];
                }
                o4p[o4] = make_float4(v[0], v[1], v[2], v[3]);
            }
        }
    }
}

extern "C" void kernel_launch(void* const* d_in, const int* in_sizes, int n_in,
                              void* d_out, int out_size) {
    const float* state = (const float*)d_in[0];
    const float* Wq    = (const float*)d_in[1];
    const float* bq    = (const float*)d_in[2];
    const float* Wk    = (const float*)d_in[3];
    const float* bk    = (const float*)d_in[4];
    float* out = (float*)d_out;

    // Not a stream op: safe under graph capture; idempotent every call.
    cudaFuncSetAttribute(attn_kernel,
                         cudaFuncAttributeMaxDynamicSharedMemorySize,
                         SMEM_BYTES);

    const int tb = in_sizes[0] / (AA * NN);  // T*B = 16384 tiles
    attn_kernel<<<tb / G2, THREADS, SMEM_BYTES>>>(state, Wq, bq, Wk, bk, out);
}

// round 16
// speedup vs baseline: 1.6756x; 1.0668x over previous
#include <cuda_runtime.h>

#define AA 64
#define NN 128
#define HH 8
#define G2 2
#define THREADS 256
#define OUTW (AA - 1)          // 63
#define OUT_PER (AA * OUTW)    // 4032 floats per (t,b) tile
#define OUT4_PER (OUT_PER / 4) // 1008 float4
#define SR4 33                 // stage row stride in float4
#define AROW 68                // att row stride in floats
#define SQR 12                 // s_q row stride in floats

#define ST_F4   (AA * SR4)                 // float4 per staged tile (2112)
#define STAGE_ITERS (G2 * AA * NN / 4 / THREADS)   // 16
#define SMEM_BYTES (G2 * ST_F4 * 16 + NN * 16 * 4 + G2 * AA * SQR * 4 \
                    + G2 * AA * HH * 4 + 8 * 128 * 8 + 2 * THREADS * 4)

typedef unsigned long long u64;

// ---- packed f32x2 helpers (Blackwell FFMA2/FADD2) ----
__device__ __forceinline__ u64 pk2(float lo, float hi) {
    u64 r;
    asm("mov.b64 %0, {%1, %2};" : "=l"(r) : "f"(lo), "f"(hi));
    return r;
}
__device__ __forceinline__ void upk2(u64 v, float &lo, float &hi) {
    asm("mov.b64 {%0, %1}, %2;" : "=f"(lo), "=f"(hi) : "l"(v));
}
__device__ __forceinline__ void ffma2(u64 &d, u64 a, u64 b) {
    asm("fma.rn.f32x2 %0, %1, %2, %0;" : "+l"(d) : "l"(a), "l"(b));
}
__device__ __forceinline__ u64 fadd2(u64 a, u64 b) {
    u64 r;
    asm("add.rn.f32x2 %0, %1, %2;" : "=l"(r) : "l"(a), "l"(b));
    return r;
}

__global__ void __launch_bounds__(THREADS, 2)
attn_kernel(const float* __restrict__ state,
            const float* __restrict__ Wq, const float* __restrict__ bq,
            const float* __restrict__ Wk, const float* __restrict__ bk,
            float* __restrict__ out)
{
    extern __shared__ __align__(16) unsigned char smem_raw[];
    float4* const s_x4 = (float4*)smem_raw;                       // [G2][ST_F4]
    float*  const s_w  = (float*)(smem_raw + G2 * ST_F4 * 16);    // NN*16
    float*  const s_q  = s_w + NN * 16;                           // [G2][AA*SQR]
    float*  const s_k  = s_q + G2 * AA * SQR;                     // [G2][AA*HH]
    u64*    const s_pp = (u64*)(s_k + G2 * AA * HH);              // [8][128] partials
    float*  const s_rm = (float*)(s_pp + 8 * 128);                // [256] max scratch
    float*  const s_rs = s_rm + THREADS;                          // [256] sum scratch

    const int tid = threadIdx.x;
    const int blk = blockIdx.x;

    // ---- weights: s_w[n*16 + 0..7] = Wq[n][:], s_w[n*16 + 8..15] = Wk[n][:]
    for (int i = tid; i < NN * HH; i += THREADS) {
        const int n = i >> 3, h = i & 7;
        s_w[n * 16 + h]     = Wq[i];
        s_w[n * 16 + 8 + h] = Wk[i];
    }

    // ---- Phase 0: coalesced stage of BOTH tiles (warp == one row, 512B)
    const float4* gsrc = (const float4*)(state + (size_t)blk * (G2 * AA * NN));
    #pragma unroll
    for (int k = 0; k < STAGE_ITERS; k++) {         // 16 iters, idx 0..4095
        const int idx = k * THREADS + tid;
        const int g = idx >> 11;                    // 0..1
        const int w = (idx >> 5) & 63;              // row within tile
        const int c = idx & 31;
        s_x4[g * ST_F4 + w * SR4 + c] = gsrc[idx];
    }
    __syncthreads();

    // ---- Phase 1: projection. thread = (mat, n-half, row); ALL 256 active.
    {
        const int mat = tid >> 7;        // 0 = Q, 1 = K (uniform per warp)
        const int nh  = (tid >> 6) & 1;  // n-half          (uniform per warp)
        const int row = tid & 63;
        const int widx = mat * 64 + row; // partial slot 0..127

        const float* bb = mat ? bk : bq;
        u64 a0[4], a1[4];
        #pragma unroll
        for (int p = 0; p < 4; p++) {
            u64 seed = 0ull;
            if (nh == 0) seed = pk2(__ldg(bb + 2 * p), __ldg(bb + 2 * p + 1));
            a0[p] = seed; a1[p] = seed;
        }

        const float4* xr0 = s_x4 + row * SR4 + nh * 16;
        const float4* xr1 = xr0 + ST_F4;
        const ulonglong2* wp =
            ((const ulonglong2*)s_w) + (nh * 64) * 4 + mat * 2;

        #pragma unroll 4
        for (int i = 0; i < 16; i++) {
            const float4 x0 = xr0[i];
            const float4 x1 = xr1[i];
            u64 xx;
            {
                const ulonglong2 w0 = wp[(4 * i + 0) * 4];
                const ulonglong2 w1 = wp[(4 * i + 0) * 4 + 1];
                xx = pk2(x0.x, x0.x);
                ffma2(a0[0], xx, w0.x); ffma2(a0[1], xx, w0.y);
                ffma2(a0[2], xx, w1.x); ffma2(a0[3], xx, w1.y);
                xx = pk2(x1.x, x1.x);
                ffma2(a1[0], xx, w0.x); ffma2(a1[1], xx, w0.y);
                ffma2(a1[2], xx, w1.x); ffma2(a1[3], xx, w1.y);
            }
            {
                const ulonglong2 w0 = wp[(4 * i + 1) * 4];
                const ulonglong2 w1 = wp[(4 * i + 1) * 4 + 1];
                xx = pk2(x0.y, x0.y);
                ffma2(a0[0], xx, w0.x); ffma2(a0[1], xx, w0.y);
                ffma2(a0[2], xx, w1.x); ffma2(a0[3], xx, w1.y);
                xx = pk2(x1.y, x1.y);
                ffma2(a1[0], xx, w0.x); ffma2(a1[1], xx, w0.y);
                ffma2(a1[2], xx, w1.x); ffma2(a1[3], xx, w1.y);
            }
            {
                const ulonglong2 w0 = wp[(4 * i + 2) * 4];
                const ulonglong2 w1 = wp[(4 * i + 2) * 4 + 1];
                xx = pk2(x0.z, x0.z);
                ffma2(a0[0], xx, w0.x); ffma2(a0[1], xx, w0.y);
                ffma2(a0[2], xx, w1.x); ffma2(a0[3], xx, w1.y);
                xx = pk2(x1.z, x1.z);
                ffma2(a1[0], xx, w0.x); ffma2(a1[1], xx, w0.y);
                ffma2(a1[2], xx, w1.x); ffma2(a1[3], xx, w1.y);
            }
            {
                const ulonglong2 w0 = wp[(4 * i + 3) * 4];
                const ulonglong2 w1 = wp[(4 * i + 3) * 4 + 1];
                xx = pk2(x0.w, x0.w);
                ffma2(a0[0], xx, w0.x); ffma2(a0[1], xx, w0.y);
                ffma2(a0[2], xx, w1.x); ffma2(a0[3], xx, w1.y);
                xx = pk2(x1.w, x1.w);
                ffma2(a1[0], xx, w0.x); ffma2(a1[1], xx, w0.y);
                ffma2(a1[2], xx, w1.x); ffma2(a1[3], xx, w1.y);
            }
        }

        // nh=1 publishes partials (dense STS.64, conflict-free)
        if (nh == 1) {
            #pragma unroll
            for (int p = 0; p < 4; p++) {
                s_pp[p * 128 + widx]       = a0[p];
                s_pp[(4 + p) * 128 + widx] = a1[p];
            }
        }
        __syncthreads();

        // nh=0 folds in partner's half and writes q/k
        if (nh == 0) {
            #pragma unroll
            for (int p = 0; p < 4; p++) {
                a0[p] = fadd2(a0[p], s_pp[p * 128 + widx]);
                a1[p] = fadd2(a1[p], s_pp[(4 + p) * 128 + widx]);
            }
            float v0, v1, v2, v3, v4, v5, v6, v7;
            if (mat == 0) {
                upk2(a0[0], v0, v1); upk2(a0[1], v2, v3);
                upk2(a0[2], v4, v5); upk2(a0[3], v6, v7);
                *(float4*)(s_q + row * SQR)     = make_float4(v0, v1, v2, v3);
                *(float4*)(s_q + row * SQR + 4) = make_float4(v4, v5, v6, v7);
                upk2(a1[0], v0, v1); upk2(a1[1], v2, v3);
                upk2(a1[2], v4, v5); upk2(a1[3], v6, v7);
                *(float4*)(s_q + AA * SQR + row * SQR)     = make_float4(v0, v1, v2, v3);
                *(float4*)(s_q + AA * SQR + row * SQR + 4) = make_float4(v4, v5, v6, v7);
            } else {
                upk2(a0[0], v0, v1); upk2(a0[1], v2, v3);
                upk2(a0[2], v4, v5); upk2(a0[3], v6, v7);
                *(float4*)(s_k + row * HH)     = make_float4(v0, v1, v2, v3);
                *(float4*)(s_k + row * HH + 4) = make_float4(v4, v5, v6, v7);
                upk2(a1[0], v0, v1); upk2(a1[1], v2, v3);
                upk2(a1[2], v4, v5); upk2(a1[3], v6, v7);
                *(float4*)(s_k + AA * HH + row * HH)     = make_float4(v0, v1, v2, v3);
                *(float4*)(s_k + AA * HH + row * HH + 4) = make_float4(v4, v5, v6, v7);
            }
        }
    }
    __syncthreads();
    // stage buffers are dead; att[g] aliases stage half g.

    // ---- Phase 2 (fused): att + softmax in (sub,row); reductions via smem
    //      scratch while att values stay in registers. No (row,sub) remap.
    {
        const int p_sub = tid >> 6;
        const int p_row = tid & 63;
        const int jbase = p_sub * 16;
        const int ridx = p_row * 4 + p_sub;   // banks 4r+s: conflict-free STS.32

        for (int g = 0; g < G2; g++) {
            const float* qg = s_q + g * AA * SQR;
            const float* kg = s_k + g * AA * HH;
            float* attg = (float*)s_x4 + g * (ST_F4 * 4);

            const float4 qa = *(const float4*)(qg + p_row * SQR);
            const float4 qb = *(const float4*)(qg + p_row * SQR + 4);
            const float qr[8] = {qa.x, qa.y, qa.z, qa.w, qb.x, qb.y, qb.z, qb.w};

            u64 at2[8];
            #pragma unroll
            for (int p = 0; p < 8; p++) at2[p] = 0ull;

            // reshape trick: kr[h][j] = k_flat[h*64 + j]; warp-uniform address
            #pragma unroll
            for (int h = 0; h < HH; h++) {
                const u64 qq = pk2(qr[h], qr[h]);
                const ulonglong2* kp = (const ulonglong2*)(kg + h * AA + jbase);
                const ulonglong2 k0 = kp[0], k1 = kp[1], k2 = kp[2], k3 = kp[3];
                ffma2(at2[0], qq, k0.x); ffma2(at2[1], qq, k0.y);
                ffma2(at2[2], qq, k1.x); ffma2(at2[3], qq, k1.y);
                ffma2(at2[4], qq, k2.x); ffma2(at2[5], qq, k2.y);
                ffma2(at2[6], qq, k3.x); ffma2(at2[7], qq, k3.y);
            }

            float a[16];
            #pragma unroll
            for (int p = 0; p < 8; p++) upk2(at2[p], a[2 * p], a[2 * p + 1]);

            // row max: local 16, then cross-sub via smem scratch
            float m = a[0];
            #pragma unroll
            for (int c = 1; c < 16; c++) m = fmaxf(m, a[c]);
            s_rm[ridx] = m;
            __syncthreads();
            const float4 mv = *(const float4*)(s_rm + p_row * 4);
            m = fmaxf(fmaxf(mv.x, mv.y), fmaxf(mv.z, mv.w));

            // exp + row sum (same scratch pattern, different buffer)
            float s = 0.f;
            #pragma unroll
            for (int c = 0; c < 16; c++) { a[c] = __expf(a[c] - m); s += a[c]; }
            s_rs[ridx] = s;
            __syncthreads();
            const float4 sv = *(const float4*)(s_rs + p_row * 4);
            const float rinv = __frcp_rn((sv.x + sv.y) + (sv.z + sv.w));

            float4* arow = (float4*)(attg + p_row * AROW + jbase);
            arow[0] = make_float4(a[0]  * rinv, a[1]  * rinv, a[2]  * rinv, a[3]  * rinv);
            arow[1] = make_float4(a[4]  * rinv, a[5]  * rinv, a[6]  * rinv, a[7]  * rinv);
            arow[2] = make_float4(a[8]  * rinv, a[9]  * rinv, a[10] * rinv, a[11] * rinv);
            arow[3] = make_float4(a[12] * rinv, a[13] * rinv, a[14] * rinv, a[15] * rinv);
        }
    }
    __syncthreads();

    // ---- Phase 3: off-diagonal gather, coalesced float4 stores -------------
    #pragma unroll
    for (int g = 0; g < G2; g++) {
        const float* attg = (const float*)s_x4 + g * (ST_F4 * 4);
        float4* o4p = (float4*)(out + (size_t)(blk * G2 + g) * OUT_PER);
        #pragma unroll
        for (int it = 0; it < 4; it++) {
            const int o4 = it * THREADS + tid;
            if (o4 < OUT4_PER) {
                const unsigned o = (unsigned)o4 * 4u;
                float v[4];
                #pragma unroll
                for (int c = 0; c < 4; c++) {
                    const unsigned oc = o + c;
                    const unsigned rr = oc / OUTW;
                    const unsigned jj = oc - rr * OUTW;
                    const unsigned j  = jj + (jj >= rr ? 1u : 0u);
                    v[c] = attg[rr * AROW + j];
                }
                o4p[o4] = make_float4(v[0], v[1], v[2], v[3]);
            }
        }
    }
}

extern "C" void kernel_launch(void* const* d_in, const int* in_sizes, int n_in,
                              void* d_out, int out_size) {
    const float* state = (const float*)d_in[0];
    const float* Wq    = (const float*)d_in[1];
    const float* bq    = (const float*)d_in[2];
    const float* Wk    = (const float*)d_in[3];
    const float* bk    = (const float*)d_in[4];
    float* out = (float*)d_out;

    // Not a stream op: safe under graph capture; idempotent every call.
    cudaFuncSetAttribute(attn_kernel,
                         cudaFuncAttributeMaxDynamicSharedMemorySize,
                         SMEM_BYTES);

    const int tb = in_sizes[0] / (AA * NN);  // T*B = 16384 tiles
    attn_kernel<<<tb / G2, THREADS, SMEM_BYTES>>>(state, Wq, bq, Wk, bk, out);
}